// round 2
// baseline (speedup 1.0000x reference)
#include <cuda_runtime.h>
#include <cuda_bf16.h>
#include <cstdint>

#define IN_FEAT   256
#define OUT_FEAT  32
#define MAXN      131072
#define MAXE      2097152
#define SCAN_B    512

// ---------------- device scratch ----------------
__device__ float g_x[MAXN * OUT_FEAT];        // projected features
__device__ int   g_cnt[MAXN];                 // per-row edge counts
__device__ int   g_rs[MAXN + 1];              // CSR row_start
__device__ int   g_cur[MAXN];                 // scatter cursors
__device__ int   g_part[SCAN_B];              // scan partials
__device__ int   g_poff[SCAN_B];              // scanned partials
__device__ uint2 g_pairs[MAXE];               // sorted (col, val_bits)

// ---------------------------------------------------------------------------
// Stage 1: x = feat @ W    (f32x2 inner, software-pipelined feat loads)
// ---------------------------------------------------------------------------
__device__ __forceinline__ void ffma2(unsigned long long& acc,
                                      unsigned long long a,
                                      unsigned long long b) {
    asm("fma.rn.f32x2 %0, %1, %2, %0;" : "+l"(acc) : "l"(a), "l"(b));
}
__device__ __forceinline__ unsigned long long pack_dup(float a) {
    unsigned long long r;
    asm("mov.b64 %0, {%1, %1};" : "=l"(r) : "f"(a));
    return r;
}

__global__ __launch_bounds__(256, 2)
void gemm_kernel(const float* __restrict__ feat,
                 const float* __restrict__ weight,
                 int n_nodes) {
    __shared__ float sW[IN_FEAT * OUT_FEAT];  // 32 KB

    const float4* wg4 = (const float4*)weight;
    float4* sw4 = (float4*)sW;
    #pragma unroll
    for (int i = threadIdx.x; i < (IN_FEAT * OUT_FEAT) / 4; i += 256)
        sw4[i] = wg4[i];
    __syncthreads();

    int row = blockIdx.x * 256 + threadIdx.x;
    if (row >= n_nodes) return;

    const float4* fr = (const float4*)(feat + (size_t)row * IN_FEAT);

    unsigned long long acc[16];
    #pragma unroll
    for (int i = 0; i < 16; i++) acc[i] = 0ull;

    // double-buffered: 4 float4 loads in flight while computing previous 16 k
    float4 cur[4];
    #pragma unroll
    for (int j = 0; j < 4; j++) cur[j] = __ldg(fr + j);

    #pragma unroll 1
    for (int blk = 0; blk < 16; blk++) {
        float4 nxt[4];
        if (blk < 15) {
            #pragma unroll
            for (int j = 0; j < 4; j++) nxt[j] = __ldg(fr + (blk + 1) * 4 + j);
        }
        #pragma unroll
        for (int j = 0; j < 4; j++) {
            float4 a4 = cur[j];
            float av[4] = {a4.x, a4.y, a4.z, a4.w};
            #pragma unroll
            for (int c = 0; c < 4; c++) {
                int k = blk * 16 + j * 4 + c;
                unsigned long long aa = pack_dup(av[c]);
                const ulonglong2* wrow = (const ulonglong2*)(sW + k * OUT_FEAT);
                #pragma unroll
                for (int i = 0; i < 8; i++) {
                    ulonglong2 b = wrow[i];   // broadcast LDS.128
                    ffma2(acc[2 * i],     aa, b.x);
                    ffma2(acc[2 * i + 1], aa, b.y);
                }
            }
        }
        #pragma unroll
        for (int j = 0; j < 4; j++) cur[j] = nxt[j];
    }

    float4* xo = (float4*)(g_x + (size_t)row * OUT_FEAT);
    #pragma unroll
    for (int i = 0; i < 8; i++) {
        float2 lo = *(float2*)&acc[2 * i];
        float2 hi = *(float2*)&acc[2 * i + 1];
        float4 v; v.x = lo.x; v.y = lo.y; v.z = hi.x; v.w = hi.y;
        xo[i] = v;
    }
}

// ---------------------------------------------------------------------------
// CSR build: zero -> histogram -> scan (3 kernels) -> scatter
// ---------------------------------------------------------------------------
__global__ void zero_cnt_kernel(int n) {
    int i = blockIdx.x * 256 + threadIdx.x;
    if (i < n) g_cnt[i] = 0;
}

__global__ void hist_kernel(const int* __restrict__ erow, int n_edges) {
    int e = blockIdx.x * 256 + threadIdx.x;
    if (e < n_edges) atomicAdd(&g_cnt[erow[e]], 1);
}

// per-block inclusive scan; writes block-local exclusive prefix + block total
__global__ void scan1_kernel(int n) {
    __shared__ int s[SCAN_B];
    int t = threadIdx.x;
    int i = blockIdx.x * SCAN_B + t;
    int v = (i < n) ? g_cnt[i] : 0;
    s[t] = v;
    __syncthreads();
    #pragma unroll
    for (int off = 1; off < SCAN_B; off <<= 1) {
        int u = (t >= off) ? s[t - off] : 0;
        __syncthreads();
        s[t] += u;
        __syncthreads();
    }
    if (i < n) g_rs[i] = s[t] - v;           // exclusive within block
    if (t == SCAN_B - 1) g_part[blockIdx.x] = s[t];
}

// scan block partials (single block)
__global__ void scan2_kernel(int nparts) {
    __shared__ int s[SCAN_B];
    int t = threadIdx.x;
    int v = (t < nparts) ? g_part[t] : 0;
    s[t] = v;
    __syncthreads();
    #pragma unroll
    for (int off = 1; off < SCAN_B; off <<= 1) {
        int u = (t >= off) ? s[t - off] : 0;
        __syncthreads();
        s[t] += u;
        __syncthreads();
    }
    if (t < nparts) g_poff[t] = s[t] - v;    // exclusive
}

__global__ void scan3_kernel(int n, int n_edges) {
    int i = blockIdx.x * 256 + threadIdx.x;
    if (i < n) {
        int v = g_rs[i] + g_poff[i >> 9];
        g_rs[i]  = v;
        g_cur[i] = v;
    }
    if (i == 0) g_rs[n] = n_edges;
}

__global__ void scatter_kernel(const float* __restrict__ vals,
                               const int* __restrict__ erow,
                               const int* __restrict__ ecol,
                               int n_edges) {
    int e = blockIdx.x * 256 + threadIdx.x;
    if (e >= n_edges) return;
    int r = erow[e];
    int pos = atomicAdd(&g_cur[r], 1);
    g_pairs[pos] = make_uint2((unsigned)ecol[e], __float_as_uint(vals[e]));
}

// ---------------------------------------------------------------------------
// Stage 2 (no atomics): out[row] = sum_e vals * x[col]   8 threads per row
// ---------------------------------------------------------------------------
__global__ __launch_bounds__(256)
void gather_kernel(float* __restrict__ out, int n_nodes) {
    int t = blockIdx.x * 256 + threadIdx.x;
    int row = t >> 3;
    if (row >= n_nodes) return;
    int q = (t & 7) << 2;

    int s = g_rs[row];
    int e = g_rs[row + 1];

    float4 acc; acc.x = acc.y = acc.z = acc.w = 0.f;

    int i = s;
    for (; i + 1 < e; i += 2) {                      // MLP 2
        uint2 p0 = g_pairs[i];
        uint2 p1 = g_pairs[i + 1];
        float4 x0 = *(const float4*)(g_x + p0.x * OUT_FEAT + q);
        float4 x1 = *(const float4*)(g_x + p1.x * OUT_FEAT + q);
        float v0 = __uint_as_float(p0.y);
        float v1 = __uint_as_float(p1.y);
        acc.x += v0 * x0.x + v1 * x1.x;
        acc.y += v0 * x0.y + v1 * x1.y;
        acc.z += v0 * x0.z + v1 * x1.z;
        acc.w += v0 * x0.w + v1 * x1.w;
    }
    if (i < e) {
        uint2 p0 = g_pairs[i];
        float4 x0 = *(const float4*)(g_x + p0.x * OUT_FEAT + q);
        float v0 = __uint_as_float(p0.y);
        acc.x += v0 * x0.x; acc.y += v0 * x0.y;
        acc.z += v0 * x0.z; acc.w += v0 * x0.w;
    }

    *(float4*)(out + row * OUT_FEAT + q) = acc;      // full coverage, no memset
}

// ---------------------------------------------------------------------------
extern "C" void kernel_launch(void* const* d_in, const int* in_sizes, int n_in,
                              void* d_out, int out_size) {
    const float* feat   = (const float*)d_in[0];
    const float* weight = (const float*)d_in[1];
    const float* vals   = (const float*)d_in[2];
    const int*   erow   = (const int*)d_in[3];
    const int*   ecol   = (const int*)d_in[4];
    float* out = (float*)d_out;

    int n_nodes = in_sizes[0] / IN_FEAT;
    int n_edges = in_sizes[2];

    int nb_nodes = (n_nodes + 255) / 256;
    int nb_edges = (n_edges + 255) / 256;
    int nb_scan  = (n_nodes + SCAN_B - 1) / SCAN_B;

    gemm_kernel<<<nb_nodes, 256>>>(feat, weight, n_nodes);

    zero_cnt_kernel<<<nb_nodes, 256>>>(n_nodes);
    hist_kernel<<<nb_edges, 256>>>(erow, n_edges);
    scan1_kernel<<<nb_scan, SCAN_B>>>(n_nodes);
    scan2_kernel<<<1, SCAN_B>>>(nb_scan);
    scan3_kernel<<<nb_nodes, 256>>>(n_nodes, n_edges);
    scatter_kernel<<<nb_edges, 256>>>(vals, erow, ecol, n_edges);

    long long work = (long long)n_nodes * 8;
    int nb_gather = (int)((work + 255) / 256);
    gather_kernel<<<nb_gather, 256>>>(out, n_nodes);
}

// round 3
// speedup vs baseline: 1.1162x; 1.1162x over previous
#include <cuda_runtime.h>
#include <cuda_bf16.h>
#include <cstdint>

#define IN_FEAT   256
#define OUT_FEAT  32
#define MAXN      131072
#define TM        256            // rows per block
#define KC        8              // k-floats per chunk (32 B per row)
#define NCHUNK    (IN_FEAT / KC) // 32

__device__ float g_x[MAXN * OUT_FEAT];   // projected features (12.8 MB)

// ---------------------------------------------------------------------------
// helpers
// ---------------------------------------------------------------------------
__device__ __forceinline__ void ffma2(unsigned long long& acc,
                                      unsigned long long a,
                                      unsigned long long b) {
    asm("fma.rn.f32x2 %0, %1, %2, %0;" : "+l"(acc) : "l"(a), "l"(b));
}
__device__ __forceinline__ unsigned long long pack_dup(float a) {
    unsigned long long r;
    asm("mov.b64 %0, {%1, %1};" : "=l"(r) : "f"(a));
    return r;
}
__device__ __forceinline__ unsigned smem_u32(const void* p) {
    return (unsigned)__cvta_generic_to_shared(p);
}
__device__ __forceinline__ void cp_async16(unsigned dst, const void* src) {
    asm volatile("cp.async.cg.shared.global [%0], [%1], 16;"
                 :: "r"(dst), "l"(src));
}
__device__ __forceinline__ void cp_commit() {
    asm volatile("cp.async.commit_group;");
}
template <int N>
__device__ __forceinline__ void cp_wait() {
    asm volatile("cp.async.wait_group %0;" :: "n"(N));
}

// ---------------------------------------------------------------------------
// Stage 1: x = feat @ W    (smem-staged feat, double-buffered cp.async,
//                           f32x2 inner product, W broadcast from smem)
// ---------------------------------------------------------------------------
__global__ __launch_bounds__(256)
void gemm_kernel(const float* __restrict__ feat,
                 const float* __restrict__ weight,
                 int n_nodes) {
    __shared__ float sW[IN_FEAT * OUT_FEAT];   // 32 KB
    __shared__ float sF[2][TM * KC];           // 2 x 8 KB  (total 48 KB)

    const int t    = threadIdx.x;
    const int row0 = blockIdx.x * TM;

    // ---- stage chunk c into buffer b: 512 x 16B, 2 ops/thread ----
    auto stage = [&](int c, int b) {
        #pragma unroll
        for (int i = 0; i < 2; i++) {
            int idx = i * 256 + t;          // 0..511
            int r   = idx >> 1;             // local row
            int s   = idx & 1;              // 16B segment within 32B chunk
            int gr  = row0 + r;
            if (gr > n_nodes - 1) gr = n_nodes - 1;   // clamp (values unused)
            const float* src = feat + (size_t)gr * IN_FEAT + c * KC + s * 4;
            unsigned dst = smem_u32(&sF[b][r * KC + s * 4]);
            cp_async16(dst, src);
        }
        cp_commit();
    };

    // prologue: kick chunk 0, then cooperatively load W (coalesced)
    stage(0, 0);
    {
        const float4* wg4 = (const float4*)weight;
        float4* sw4 = (float4*)sW;
        #pragma unroll
        for (int i = 0; i < (IN_FEAT * OUT_FEAT) / 4 / 256; i++)
            sw4[i * 256 + t] = wg4[i * 256 + t];
    }

    unsigned long long acc[16];
    #pragma unroll
    for (int i = 0; i < 16; i++) acc[i] = 0ull;

    #pragma unroll 1
    for (int c = 0; c < NCHUNK; c++) {
        int b = c & 1;
        if (c + 1 < NCHUNK) {
            stage(c + 1, b ^ 1);
            cp_wait<1>();           // chunk c arrived
        } else {
            cp_wait<0>();
        }
        __syncthreads();            // data visible to all; W ready on c==0

        // compute chunk c from sF[b]
        #pragma unroll
        for (int j = 0; j < KC / 4; j++) {
            float4 a4 = *(const float4*)(&sF[b][t * KC + j * 4]);
            float av[4] = {a4.x, a4.y, a4.z, a4.w};
            #pragma unroll
            for (int s2 = 0; s2 < 4; s2++) {
                int k = c * KC + j * 4 + s2;
                unsigned long long aa = pack_dup(av[s2]);
                const ulonglong2* wrow = (const ulonglong2*)(sW + k * OUT_FEAT);
                #pragma unroll
                for (int i = 0; i < 8; i++) {
                    ulonglong2 bb = wrow[i];     // broadcast LDS.128
                    ffma2(acc[2 * i],     aa, bb.x);
                    ffma2(acc[2 * i + 1], aa, bb.y);
                }
            }
        }
        __syncthreads();            // buffer b free for reuse at c+2
    }

    int row = row0 + t;
    if (row < n_nodes) {
        float4* xo = (float4*)(g_x + (size_t)row * OUT_FEAT);
        #pragma unroll
        for (int i = 0; i < 8; i++) {
            float2 lo = *(float2*)&acc[2 * i];
            float2 hi = *(float2*)&acc[2 * i + 1];
            float4 v; v.x = lo.x; v.y = lo.y; v.z = hi.x; v.w = hi.y;
            xo[i] = v;
        }
    }
}

// ---------------------------------------------------------------------------
// Stage 2: out[row[e]] += vals[e] * x[col[e]]
// 8 threads per edge, float4 gather + red.global.add.v4.f32 scatter.
// (R1 version — measured 61 us, near the RED/LSU structural floor.)
// ---------------------------------------------------------------------------
__global__ __launch_bounds__(256)
void spmm_kernel(const float* __restrict__ vals,
                 const int* __restrict__ erow,
                 const int* __restrict__ ecol,
                 float* __restrict__ out,
                 int n_edges) {
    int idx = blockIdx.x * 256 + threadIdx.x;
    int e = idx >> 3;
    if (e >= n_edges) return;
    int q = (idx & 7) << 2;

    int   c = __ldg(ecol + e);
    int   r = __ldg(erow + e);
    float v = __ldg(vals + e);

    float4 xv = *(const float4*)(g_x + c * OUT_FEAT + q);
    float4 m;
    m.x = v * xv.x; m.y = v * xv.y; m.z = v * xv.z; m.w = v * xv.w;

    float* dst = out + r * OUT_FEAT + q;
    asm volatile("red.global.add.v4.f32 [%0], {%1, %2, %3, %4};"
                 :: "l"(dst), "f"(m.x), "f"(m.y), "f"(m.z), "f"(m.w)
                 : "memory");
}

// ---------------------------------------------------------------------------
extern "C" void kernel_launch(void* const* d_in, const int* in_sizes, int n_in,
                              void* d_out, int out_size) {
    const float* feat   = (const float*)d_in[0];
    const float* weight = (const float*)d_in[1];
    const float* vals   = (const float*)d_in[2];
    const int*   erow   = (const int*)d_in[3];
    const int*   ecol   = (const int*)d_in[4];
    float* out = (float*)d_out;

    int n_nodes = in_sizes[0] / IN_FEAT;
    int n_edges = in_sizes[2];

    cudaMemsetAsync(out, 0, (size_t)out_size * sizeof(float), 0);

    int gemm_blocks = (n_nodes + TM - 1) / TM;
    gemm_kernel<<<gemm_blocks, 256>>>(feat, weight, n_nodes);

    long long work = (long long)n_edges * 8;
    int spmm_blocks = (int)((work + 255) / 256);
    spmm_kernel<<<spmm_blocks, 256>>>(vals, erow, ecol, out, n_edges);
}

// round 4
// speedup vs baseline: 1.2837x; 1.1500x over previous
#include <cuda_runtime.h>
#include <cuda_bf16.h>
#include <cstdint>

#define IN_FEAT   256
#define OUT_FEAT  32
#define MAXN      131072
#define TM        256            // rows per block
#define NT        128            // threads per block (2 rows each)
#define KC        8              // k-floats per chunk (32 B per row)
#define NCHUNK    (IN_FEAT / KC) // 32

__device__ float g_x[MAXN * OUT_FEAT];   // projected features (12.8 MB)

// ---------------------------------------------------------------------------
// helpers
// ---------------------------------------------------------------------------
__device__ __forceinline__ void ffma2(unsigned long long& acc,
                                      unsigned long long a,
                                      unsigned long long b) {
    asm("fma.rn.f32x2 %0, %1, %2, %0;" : "+l"(acc) : "l"(a), "l"(b));
}
__device__ __forceinline__ unsigned long long pack_dup(float a) {
    unsigned long long r;
    asm("mov.b64 %0, {%1, %1};" : "=l"(r) : "f"(a));
    return r;
}
__device__ __forceinline__ unsigned smem_u32(const void* p) {
    return (unsigned)__cvta_generic_to_shared(p);
}
__device__ __forceinline__ void cp_async16(unsigned dst, const void* src) {
    asm volatile("cp.async.cg.shared.global [%0], [%1], 16;"
                 :: "r"(dst), "l"(src));
}
__device__ __forceinline__ void cp_commit() {
    asm volatile("cp.async.commit_group;");
}
template <int N>
__device__ __forceinline__ void cp_wait() {
    asm volatile("cp.async.wait_group %0;" :: "n"(N));
}

// ---------------------------------------------------------------------------
// Stage 1: x = feat @ W
// 2 rows per thread: each broadcast W LDS.128 feeds 4 FFMA2 (was 2),
// halving the shared-load pressure that bound the previous version.
// Double-buffered cp.async staging of feat chunks.
// ---------------------------------------------------------------------------
__global__ __launch_bounds__(NT)
void gemm_kernel(const float* __restrict__ feat,
                 const float* __restrict__ weight,
                 int n_nodes) {
    __shared__ float sW[IN_FEAT * OUT_FEAT];   // 32 KB
    __shared__ float sF[2][TM * KC];           // 2 x 8 KB  (total 48 KB)

    const int t    = threadIdx.x;              // 0..127
    const int row0 = blockIdx.x * TM;

    // stage chunk c into buffer b: 512 x 16B, 4 ops/thread
    auto stage = [&](int c, int b) {
        #pragma unroll
        for (int i = 0; i < 4; i++) {
            int idx = i * NT + t;               // 0..511
            int r   = idx >> 1;                 // local row 0..255
            int s   = idx & 1;                  // 16B segment
            int gr  = row0 + r;
            if (gr > n_nodes - 1) gr = n_nodes - 1;
            const float* src = feat + (size_t)gr * IN_FEAT + c * KC + s * 4;
            cp_async16(smem_u32(&sF[b][r * KC + s * 4]), src);
        }
        cp_commit();
    };

    stage(0, 0);
    {   // cooperative W load: 2048 float4 / 128 threads
        const float4* wg4 = (const float4*)weight;
        float4* sw4 = (float4*)sW;
        #pragma unroll
        for (int i = 0; i < (IN_FEAT * OUT_FEAT) / 4 / NT; i++)
            sw4[i * NT + t] = wg4[i * NT + t];
    }

    unsigned long long accA[16], accB[16];
    #pragma unroll
    for (int i = 0; i < 16; i++) { accA[i] = 0ull; accB[i] = 0ull; }

    #pragma unroll 1
    for (int c = 0; c < NCHUNK; c++) {
        int b = c & 1;
        if (c + 1 < NCHUNK) { stage(c + 1, b ^ 1); cp_wait<1>(); }
        else                { cp_wait<0>(); }
        __syncthreads();

        #pragma unroll
        for (int j = 0; j < KC / 4; j++) {
            float4 aA = *(const float4*)(&sF[b][t * KC + j * 4]);
            float4 aB = *(const float4*)(&sF[b][(t + NT) * KC + j * 4]);
            float avA[4] = {aA.x, aA.y, aA.z, aA.w};
            float avB[4] = {aB.x, aB.y, aB.z, aB.w};
            #pragma unroll
            for (int s2 = 0; s2 < 4; s2++) {
                int k = c * KC + j * 4 + s2;
                unsigned long long dA = pack_dup(avA[s2]);
                unsigned long long dB = pack_dup(avB[s2]);
                const ulonglong2* wrow = (const ulonglong2*)(sW + k * OUT_FEAT);
                #pragma unroll
                for (int i = 0; i < 8; i++) {
                    ulonglong2 bb = wrow[i];          // broadcast LDS.128
                    ffma2(accA[2 * i],     dA, bb.x);
                    ffma2(accA[2 * i + 1], dA, bb.y);
                    ffma2(accB[2 * i],     dB, bb.x);
                    ffma2(accB[2 * i + 1], dB, bb.y);
                }
            }
        }
        __syncthreads();
    }

    // epilogue: write both rows
    int rowA = row0 + t;
    int rowB = row0 + NT + t;
    if (rowA < n_nodes) {
        float4* xo = (float4*)(g_x + (size_t)rowA * OUT_FEAT);
        #pragma unroll
        for (int i = 0; i < 8; i++) {
            float2 lo = *(float2*)&accA[2 * i];
            float2 hi = *(float2*)&accA[2 * i + 1];
            float4 v; v.x = lo.x; v.y = lo.y; v.z = hi.x; v.w = hi.y;
            xo[i] = v;
        }
    }
    if (rowB < n_nodes) {
        float4* xo = (float4*)(g_x + (size_t)rowB * OUT_FEAT);
        #pragma unroll
        for (int i = 0; i < 8; i++) {
            float2 lo = *(float2*)&accB[2 * i];
            float2 hi = *(float2*)&accB[2 * i + 1];
            float4 v; v.x = lo.x; v.y = lo.y; v.z = hi.x; v.w = hi.y;
            xo[i] = v;
        }
    }
}

// ---------------------------------------------------------------------------
// Stage 2: out[row[e]] += vals[e] * x[col[e]]
// 8 threads/edge, float4 gather + red.global.add.v4.f32.
// Measured at the REDG spread-address floor (12.8M lane-ops x 1.29 cyc).
// ---------------------------------------------------------------------------
__global__ __launch_bounds__(256)
void spmm_kernel(const float* __restrict__ vals,
                 const int* __restrict__ erow,
                 const int* __restrict__ ecol,
                 float* __restrict__ out,
                 int n_edges) {
    int idx = blockIdx.x * 256 + threadIdx.x;
    int e = idx >> 3;
    if (e >= n_edges) return;
    int q = (idx & 7) << 2;

    int   c = __ldg(ecol + e);
    int   r = __ldg(erow + e);
    float v = __ldg(vals + e);

    float4 xv = *(const float4*)(g_x + c * OUT_FEAT + q);
    float4 m;
    m.x = v * xv.x; m.y = v * xv.y; m.z = v * xv.z; m.w = v * xv.w;

    float* dst = out + r * OUT_FEAT + q;
    asm volatile("red.global.add.v4.f32 [%0], {%1, %2, %3, %4};"
                 :: "l"(dst), "f"(m.x), "f"(m.y), "f"(m.z), "f"(m.w)
                 : "memory");
}

// ---------------------------------------------------------------------------
extern "C" void kernel_launch(void* const* d_in, const int* in_sizes, int n_in,
                              void* d_out, int out_size) {
    const float* feat   = (const float*)d_in[0];
    const float* weight = (const float*)d_in[1];
    const float* vals   = (const float*)d_in[2];
    const int*   erow   = (const int*)d_in[3];
    const int*   ecol   = (const int*)d_in[4];
    float* out = (float*)d_out;

    int n_nodes = in_sizes[0] / IN_FEAT;
    int n_edges = in_sizes[2];

    cudaMemsetAsync(out, 0, (size_t)out_size * sizeof(float), 0);

    int gemm_blocks = (n_nodes + TM - 1) / TM;
    gemm_kernel<<<gemm_blocks, NT>>>(feat, weight, n_nodes);

    long long work = (long long)n_edges * 8;
    int spmm_blocks = (int)((work + 255) / 256);
    spmm_kernel<<<spmm_blocks, 256>>>(vals, erow, ecol, out, n_edges);
}

// round 5
// speedup vs baseline: 1.7183x; 1.3386x over previous
#include <cuda_runtime.h>
#include <cuda_bf16.h>
#include <cstdint>

#define IN_FEAT   256
#define OUT_FEAT  32
#define MAXN      131072
#define TM        256            // rows per block
#define NT        256            // threads (8 warps, 32 rows each)
#define KCH       32             // k-floats per staged chunk
#define NCHUNK    (IN_FEAT / KCH)
#define SFP       36             // padded floats per staged row (bank-conflict-free)
#define KP        260            // padded k-stride of transposed W

// dynamic smem layout: [ sWt: 32*KP uint (tf32) ][ sF: 2 * TM*SFP float ]
#define SWT_ELEMS (OUT_FEAT * KP)
#define SF_ELEMS  (TM * SFP)
#define SMEM_BYTES ((SWT_ELEMS + 2 * SF_ELEMS) * 4)

__device__ float g_x[MAXN * OUT_FEAT];   // projected features (12.8 MB)

// ---------------------------------------------------------------------------
// helpers
// ---------------------------------------------------------------------------
__device__ __forceinline__ unsigned smem_u32(const void* p) {
    return (unsigned)__cvta_generic_to_shared(p);
}
__device__ __forceinline__ void cp_async16(unsigned dst, const void* src) {
    asm volatile("cp.async.cg.shared.global [%0], [%1], 16;"
                 :: "r"(dst), "l"(src));
}
__device__ __forceinline__ void cp_commit() {
    asm volatile("cp.async.commit_group;");
}
template <int N>
__device__ __forceinline__ void cp_wait() {
    asm volatile("cp.async.wait_group %0;" :: "n"(N));
}
__device__ __forceinline__ unsigned f2tf32(float f) {
    unsigned r;
    asm("cvt.rna.tf32.f32 %0, %1;" : "=r"(r) : "f"(f));
    return r;
}
__device__ __forceinline__ void mma_tf32(float& c0, float& c1, float& c2, float& c3,
                                         unsigned a0, unsigned a1, unsigned a2, unsigned a3,
                                         unsigned b0, unsigned b1) {
    asm volatile("mma.sync.aligned.m16n8k8.row.col.f32.tf32.tf32.f32 "
                 "{%0,%1,%2,%3}, {%4,%5,%6,%7}, {%8,%9}, {%0,%1,%2,%3};"
                 : "+f"(c0), "+f"(c1), "+f"(c2), "+f"(c3)
                 : "r"(a0), "r"(a1), "r"(a2), "r"(a3), "r"(b0), "r"(b1));
}

// ---------------------------------------------------------------------------
// Stage 1: x = feat @ W   (TF32 tensor-core GEMM, cp.async double-buffered)
// ---------------------------------------------------------------------------
__global__ __launch_bounds__(NT)
void gemm_kernel(const float* __restrict__ feat,
                 const float* __restrict__ weight,
                 int n_nodes) {
    extern __shared__ char smem[];
    unsigned* sWt = (unsigned*)smem;                       // [32][KP] tf32
    float*    sF  = (float*)(smem + SWT_ELEMS * 4);        // [2][TM][SFP]

    const int t    = threadIdx.x;
    const int warp = t >> 5;
    const int lane = t & 31;
    const int gid  = lane >> 2;      // groupID 0..7
    const int tid4 = lane & 3;       // threadID_in_group 0..3
    const int row0 = blockIdx.x * TM;

    // stage chunk c (KCH floats per row) into buffer b: TM*8 16B segments
    auto stage = [&](int c, int b) {
        #pragma unroll
        for (int i = 0; i < (TM * 8) / NT; i++) {          // 8 segs/row
            int idx = i * NT + t;
            int r   = idx >> 3;
            int s   = idx & 7;
            int gr  = row0 + r;
            if (gr > n_nodes - 1) gr = n_nodes - 1;
            const float* src = feat + (size_t)gr * IN_FEAT + c * KCH + s * 4;
            cp_async16(smem_u32(&sF[b * SF_ELEMS + r * SFP + s * 4]), src);
        }
        cp_commit();
    };

    stage(0, 0);

    // stage W transposed + pre-converted to tf32: sWt[n][k]
    #pragma unroll
    for (int i = 0; i < (IN_FEAT * OUT_FEAT) / NT; i++) {
        int idx = i * NT + t;
        int k = idx >> 5;
        int n = idx & 31;
        sWt[n * KP + k] = f2tf32(weight[idx]);
    }

    float acc[2][4][4];
    #pragma unroll
    for (int m = 0; m < 2; m++)
        #pragma unroll
        for (int n = 0; n < 4; n++)
            #pragma unroll
            for (int i = 0; i < 4; i++) acc[m][n][i] = 0.f;

    #pragma unroll 1
    for (int c = 0; c < NCHUNK; c++) {
        int b = c & 1;
        if (c + 1 < NCHUNK) { stage(c + 1, b ^ 1); cp_wait<1>(); }
        else                { cp_wait<0>(); }
        __syncthreads();

        const float* fb = &sF[b * SF_ELEMS];
        #pragma unroll
        for (int ks = 0; ks < KCH / 8; ks++) {
            int kl = ks * 8;                 // k within chunk
            int kg = c * KCH + kl;           // global k

            // B fragments: 4 n-tiles x 2 regs (already tf32)
            unsigned bf[4][2];
            #pragma unroll
            for (int n = 0; n < 4; n++) {
                const unsigned* wp = &sWt[(n * 8 + gid) * KP + kg + tid4];
                bf[n][0] = wp[0];
                bf[n][1] = wp[4];
            }

            // A fragments: 2 m-tiles x 4 regs
            unsigned af[2][4];
            #pragma unroll
            for (int m = 0; m < 2; m++) {
                int rb = warp * 32 + m * 16 + gid;
                const float* ap0 = &fb[rb * SFP + kl + tid4];
                const float* ap1 = &fb[(rb + 8) * SFP + kl + tid4];
                af[m][0] = f2tf32(ap0[0]);
                af[m][1] = f2tf32(ap1[0]);
                af[m][2] = f2tf32(ap0[4]);
                af[m][3] = f2tf32(ap1[4]);
            }

            #pragma unroll
            for (int n = 0; n < 4; n++)
                #pragma unroll
                for (int m = 0; m < 2; m++)
                    mma_tf32(acc[m][n][0], acc[m][n][1], acc[m][n][2], acc[m][n][3],
                             af[m][0], af[m][1], af[m][2], af[m][3],
                             bf[n][0], bf[n][1]);
        }
        __syncthreads();
    }

    // epilogue: c0:(gid, 2*tid4) c1:(gid, 2*tid4+1) c2:(gid+8, ..) c3
    #pragma unroll
    for (int m = 0; m < 2; m++) {
        int r0 = row0 + warp * 32 + m * 16 + gid;
        #pragma unroll
        for (int n = 0; n < 4; n++) {
            int col = n * 8 + 2 * tid4;
            if (r0 < n_nodes) {
                float2 v = make_float2(acc[m][n][0], acc[m][n][1]);
                *(float2*)(g_x + (size_t)r0 * OUT_FEAT + col) = v;
            }
            if (r0 + 8 < n_nodes) {
                float2 v = make_float2(acc[m][n][2], acc[m][n][3]);
                *(float2*)(g_x + (size_t)(r0 + 8) * OUT_FEAT + col) = v;
            }
        }
    }
}

// ---------------------------------------------------------------------------
// Stage 2: out[row[e]] += vals[e] * x[col[e]]
// 8 threads/edge, float4 gather + red.global.add.v4.f32 (at REDG lane floor).
// ---------------------------------------------------------------------------
__global__ __launch_bounds__(256)
void spmm_kernel(const float* __restrict__ vals,
                 const int* __restrict__ erow,
                 const int* __restrict__ ecol,
                 float* __restrict__ out,
                 int n_edges) {
    int idx = blockIdx.x * 256 + threadIdx.x;
    int e = idx >> 3;
    if (e >= n_edges) return;
    int q = (idx & 7) << 2;

    int   c = __ldg(ecol + e);
    int   r = __ldg(erow + e);
    float v = __ldg(vals + e);

    float4 xv = *(const float4*)(g_x + c * OUT_FEAT + q);
    float4 m;
    m.x = v * xv.x; m.y = v * xv.y; m.z = v * xv.z; m.w = v * xv.w;

    float* dst = out + r * OUT_FEAT + q;
    asm volatile("red.global.add.v4.f32 [%0], {%1, %2, %3, %4};"
                 :: "l"(dst), "f"(m.x), "f"(m.y), "f"(m.z), "f"(m.w)
                 : "memory");
}

// ---------------------------------------------------------------------------
extern "C" void kernel_launch(void* const* d_in, const int* in_sizes, int n_in,
                              void* d_out, int out_size) {
    const float* feat   = (const float*)d_in[0];
    const float* weight = (const float*)d_in[1];
    const float* vals   = (const float*)d_in[2];
    const int*   erow   = (const int*)d_in[3];
    const int*   ecol   = (const int*)d_in[4];
    float* out = (float*)d_out;

    int n_nodes = in_sizes[0] / IN_FEAT;
    int n_edges = in_sizes[2];

    cudaMemsetAsync(out, 0, (size_t)out_size * sizeof(float), 0);

    cudaFuncSetAttribute(gemm_kernel,
                         cudaFuncAttributeMaxDynamicSharedMemorySize, SMEM_BYTES);
    int gemm_blocks = (n_nodes + TM - 1) / TM;
    gemm_kernel<<<gemm_blocks, NT, SMEM_BYTES>>>(feat, weight, n_nodes);

    long long work = (long long)n_edges * 8;
    int spmm_blocks = (int)((work + 255) / 256);
    spmm_kernel<<<spmm_blocks, 256>>>(vals, erow, ecol, out, n_edges);
}